// round 16
// baseline (speedup 1.0000x reference)
#include <cuda_runtime.h>
#include <cuda_fp16.h>
#include <cstdint>

#define BB    2
#define NN    65536
#define KK    16
#define CIN   64
#define CADD  3
#define CMID  16
#define COUT  128
#define INF   1072
#define INFP  1088
#define MTP   16            // points per pconv block
#define PTS   (BB*NN)

typedef unsigned long long ull;
typedef unsigned int u32;
typedef unsigned short u16;

// pconv smem geometry
#define FP_PITCH 176                 // bytes per k-row of feat (88 fp16; 12-bank residue)
#define FP_PT    (KK*FP_PITCH)       // 2816 B per point
#define WN_PITCH 48                  // bytes per k-row of wn (24 fp16)
#define WN_PT    (KK*WN_PITCH)       // 768 B per point
#define FEAT_BYTES (MTP*FP_PT)       // 45056
#define WN_BYTES   (MTP*WN_PT)       // 12288
#define PCONV_SMEM (FEAT_BYTES+WN_BYTES)   // 57344

// -------- device scratch: fp16 planes (zero-init covers all pads) --------
__device__ __align__(16) u16 g_A [(size_t)PTS * INFP];   // pconv, fp16
__device__ __align__(16) u16 g_Bh[COUT * INFP];          // W, fp16

// ---------------- helpers ----------------
__device__ __forceinline__ u32 cvt2h(float lo, float hi){
    u32 d; asm("cvt.rn.f16x2.f32 %0, %1, %2;" : "=r"(d) : "f"(hi), "f"(lo));
    return d;
}
__device__ __forceinline__ u32 s2u(const void* p){
    u32 a; asm("{ .reg .u64 t; cvta.to.shared.u64 t, %1; cvt.u32.u64 %0, t; }" : "=r"(a) : "l"(p)); return a;
}
__device__ __forceinline__ void sts32(u32 addr, u32 v){
    asm volatile("st.shared.u32 [%0], %1;" :: "r"(addr), "r"(v) : "memory");
}
__device__ __forceinline__ void sts16(u32 addr, u16 v){
    asm volatile("st.shared.u16 [%0], %1;" :: "r"(addr), "h"(v) : "memory");
}
__device__ __forceinline__ void cp16(u32 dst, const void* src){
    asm volatile("cp.async.cg.shared.global [%0], [%1], 16;" :: "r"(dst), "l"(src));
}

#define LDSM4(rr, addr) \
    asm volatile("ldmatrix.sync.aligned.m8n8.x4.shared.b16 {%0,%1,%2,%3}, [%4];" \
        : "=r"((rr)[0]), "=r"((rr)[1]), "=r"((rr)[2]), "=r"((rr)[3]) : "r"(addr))

#define LDSM4T(rr, addr) \
    asm volatile("ldmatrix.sync.aligned.m8n8.x4.trans.shared.b16 {%0,%1,%2,%3}, [%4];" \
        : "=r"((rr)[0]), "=r"((rr)[1]), "=r"((rr)[2]), "=r"((rr)[3]) : "r"(addr))

#define MMAF16(d, a, b0, b1) \
    asm volatile("mma.sync.aligned.m16n8k16.row.col.f32.f16.f16.f32 " \
        "{%0,%1,%2,%3},{%4,%5,%6,%7},{%8,%9},{%0,%1,%2,%3};" \
        : "+f"((d)[0]), "+f"((d)[1]), "+f"((d)[2]), "+f"((d)[3]) \
        : "r"((a)[0]), "r"((a)[1]), "r"((a)[2]), "r"((a)[3]), "r"(b0), "r"(b1))

// ---------------- W prelude: fp16 ----------------
__global__ void wb_kernel(const float* __restrict__ W){
    int id = blockIdx.x * 256 + threadIdx.x;
    if (id < COUT * INFP) {
        int o = id / INFP, i = id % INFP;
        float w = (i < INF) ? W[o * INF + i] : 0.0f;
        g_Bh[id] = __half_as_ushort(__float2half_rn(w));
    }
}

// ---------------- kernel A: pconv via tensor-core mma ----------------
// Per point: C[c][j] = sum_k featT[c][k] * wn[k][j], 5 m-tiles x 2 n-tiles of m16n8k16.
// feat smem [k][c] fp16 (pitch 176B), wn smem [k][j] fp16 (pitch 48B); ldmatrix.trans
// lifts the transposed fragments.
__global__ __launch_bounds__(128, 3)
void pconv_mma_kernel(const float* __restrict__ input_feat,
                      const int* __restrict__ nbr,
                      const float* __restrict__ wn,
                      const float* __restrict__ addf)
{
    extern __shared__ char sm[];
    const u32 fs = s2u(sm);
    const u32 ws = fs + FEAT_BYTES;
    const int t = threadIdx.x, warp = t >> 5, lane = t & 31;
    const int bid = blockIdx.x;
    const int b  = bid / (NN / MTP);
    const int m0 = (bid % (NN / MTP)) * MTP;

    // zero smem (covers c-pads)
    #pragma unroll
    for (int i = 0; i < PCONV_SMEM / (128 * 16); i++)
        *(uint4*)(sm + (t + i * 128) * 16) = make_uint4(0, 0, 0, 0);
    __syncthreads();

    // ---- gather feat: 256 (pt,k) rows; warp handles 64; lane = c-pair ----
    {
        const int rbase = warp * 64;
        const size_t nb = (size_t)(b * NN + m0) * KK + rbase;
        int idx0 = nbr[nb + lane];
        int idx1 = nbr[nb + 32 + lane];
        idx0 = min(max(idx0, 0), NN - 1);
        idx1 = min(max(idx1, 0), NN - 1);
        #pragma unroll 4
        for (int j = 0; j < 32; j++) {
            const int r0 = rbase + j, r1 = rbase + 32 + j;
            const int i0 = __shfl_sync(0xffffffffu, idx0, j);
            const int i1 = __shfl_sync(0xffffffffu, idx1, j);
            float2 v0 = ((const float2*)(input_feat + ((size_t)b * NN + (size_t)i0) * CIN))[lane];
            float2 v1 = ((const float2*)(input_feat + ((size_t)b * NN + (size_t)i1) * CIN))[lane];
            sts32(fs + (r0 >> 4) * FP_PT + (r0 & 15) * FP_PITCH + lane * 4, cvt2h(v0.x, v0.y));
            sts32(fs + (r1 >> 4) * FP_PT + (r1 & 15) * FP_PITCH + lane * 4, cvt2h(v1.x, v1.y));
        }
    }
    // ---- wn: 256 rows of 16 floats; 4 rows per instr (8 lanes/row) ----
    {
        const int rbase = warp * 64;
        const float* wsrc = wn + ((size_t)(b * NN + m0) * KK + rbase) * CMID;
        #pragma unroll 4
        for (int rr = 0; rr < 64; rr += 4) {
            const int rloc = rr + (lane >> 3);
            const int r = rbase + rloc;
            const int jp = lane & 7;
            float2 v = ((const float2*)(wsrc + rloc * CMID))[jp];
            sts32(ws + (r >> 4) * WN_PT + (r & 15) * WN_PITCH + jp * 4, cvt2h(v.x, v.y));
        }
    }
    // ---- addf -> c = 64..66 ----
    {
        const float* as = addf + (size_t)(b * NN + m0) * KK * CADD;
        #pragma unroll
        for (int i = t; i < MTP * KK * CADD; i += 128) {
            float v = as[i];
            const int r = i / 3, c = 64 + i % 3;
            sts16(fs + (r >> 4) * FP_PT + (r & 15) * FP_PITCH + c * 2,
                  __half_as_ushort(__float2half_rn(v)));
        }
    }
    __syncthreads();

    // ---- mma: warp processes points 4*warp .. 4*warp+3 ----
    const int kA   = (lane & 7) + ((lane >> 4) & 1) * 8;
    const int colA = ((lane >> 3) & 1) * 16;
    const int kB   = (lane & 7) + ((lane >> 3) & 1) * 8;
    const int colB = ((lane >> 4) & 1) * 16;
    const int gid = lane >> 2, tid4 = lane & 3;

    #pragma unroll
    for (int pp = 0; pp < 4; pp++) {
        const int pl = warp * 4 + pp;
        const size_t pt = (size_t)(b * NN + m0 + pl);
        const u32 fb = fs + pl * FP_PT + kA * FP_PITCH + colA;
        const u32 wbp = ws + pl * WN_PT + kB * WN_PITCH + colB;
        u32* dst = (u32*)(g_A + pt * INFP);

        u32 bfr[4];
        LDSM4T(bfr, wbp);
        #pragma unroll
        for (int mt = 0; mt < 5; mt++) {
            u32 afr[4];
            LDSM4T(afr, fb + mt * 32);
            float D0[4] = {0.f,0.f,0.f,0.f}, D1[4] = {0.f,0.f,0.f,0.f};
            MMAF16(D0, afr, bfr[0], bfr[1]);   // n-tile 0: j = 0..7
            MMAF16(D1, afr, bfr[2], bfr[3]);   // n-tile 1: j = 8..15
            const int c0 = mt * 16 + gid;
            if (c0 < 67) {
                dst[(c0 * 16 + tid4 * 2) >> 1]     = cvt2h(D0[0], D0[1]);
                dst[(c0 * 16 + 8 + tid4 * 2) >> 1] = cvt2h(D1[0], D1[1]);
            }
            if (c0 + 8 < 67) {
                dst[((c0 + 8) * 16 + tid4 * 2) >> 1]     = cvt2h(D0[2], D0[3]);
                dst[((c0 + 8) * 16 + 8 + tid4 * 2) >> 1] = cvt2h(D1[2], D1[3]);
            }
        }
    }
}

// ---------------- kernel B: single-term fp16 mma.sync GEMM (round-15, validated) ----------------
#define CK       32
#define NCH      (INFP/CK)        // 34
#define PITCH    80
#define PLP      (128*PITCH)
#define STG      (2*PLP)
#define SMEM_GEMM (2*STG)         // 40960

__device__ __forceinline__ void load_chunk(u32 sbase, int kc, size_t tile0, int t)
{
    const u16* gA = g_A + tile0 * INFP;
    #pragma unroll
    for (int it = 0; it < 4; it++) {
        const int p   = it >> 1;
        const int rem = t + (it & 1) * 256;
        const int row = rem >> 2, q = rem & 3;
        const u16* g = (p == 0) ? gA : g_Bh;
        cp16(sbase + p * PLP + row * PITCH + q * 16,
             g + (size_t)row * INFP + kc * CK + q * 8);
    }
    asm volatile("cp.async.commit_group;" ::: "memory");
}

__global__ __launch_bounds__(256, 2)
void gemm_kernel(const float* __restrict__ bias, float* __restrict__ out)
{
    extern __shared__ char smem[];
    const u32 sb = s2u(smem);
    const int t = threadIdx.x, wid = t >> 5, lane = t & 31;
    const size_t tile0 = (size_t)blockIdx.x * 128;
    const int m0w = (wid & 3) * 32;
    const int n0w = (wid >> 2) * 64;

    float D[2][8][4] = {};

    const u32 a_base = (u32)((m0w + (lane & 15)) * PITCH + ((lane >> 4) & 1) * 16);
    const u32 b_base = (u32)((n0w + ((lane >> 4) & 1) * 8 + (lane & 7)) * PITCH
                             + ((lane >> 3) & 1) * 16);

    load_chunk(sb, 0, tile0, t);
    load_chunk(sb + STG, 1, tile0, t);

    for (int c = 0; c < NCH; c++) {
        const int st = c & 1;
        if (c < NCH - 1) asm volatile("cp.async.wait_group 1;" ::: "memory");
        else             asm volatile("cp.async.wait_group 0;" ::: "memory");
        __syncthreads();

        const u32 AA = sb + st * STG;
        const u32 BH = AA + PLP;

        #pragma unroll
        for (int ks = 0; ks < 2; ks++) {
            u32 aa[2][4];
            #pragma unroll
            for (int mt = 0; mt < 2; mt++)
                LDSM4(aa[mt], AA + a_base + mt * 16 * PITCH + ks * 32);
            #pragma unroll
            for (int np = 0; np < 4; np++) {
                u32 bh[4];
                LDSM4(bh, BH + b_base + np * 16 * PITCH + ks * 32);
                #pragma unroll
                for (int mt = 0; mt < 2; mt++) {
                    MMAF16(D[mt][2*np],   aa[mt], bh[0], bh[1]);
                    MMAF16(D[mt][2*np+1], aa[mt], bh[2], bh[3]);
                }
            }
        }
        __syncthreads();
        if (c + 2 < NCH) load_chunk(sb + st * STG, c + 2, tile0, t);
    }

    const int gid = lane >> 2, tid4 = lane & 3;
    #pragma unroll
    for (int nt = 0; nt < 8; nt++) {
        const int col = n0w + nt * 8 + tid4 * 2;
        const float2 bp = *(const float2*)(bias + col);
        #pragma unroll
        for (int mt = 0; mt < 2; mt++) {
            const float* Dp = D[mt][nt];
            const size_t row = tile0 + m0w + mt * 16 + gid;
            *(float2*)(out + row * COUT + col)       = make_float2(Dp[0] + bp.x, Dp[1] + bp.y);
            *(float2*)(out + (row + 8) * COUT + col) = make_float2(Dp[2] + bp.x, Dp[3] + bp.y);
        }
    }
}

// ---------------- launch ----------------
extern "C" void kernel_launch(void* const* d_in, const int* in_sizes, int n_in,
                              void* d_out, int out_size)
{
    const float* input_feat = 0;   // 8388608
    const int*   nbr        = 0;   // 2097152 (int32)
    const float* wn         = 0;   // 33554432
    const float* addf       = 0;   // 6291456
    const float* W          = 0;   // 137216
    const float* bias       = 0;   // 128

    for (int i = 0; i < n_in; i++) {
        switch (in_sizes[i]) {
            case BB * NN * CIN:        input_feat = (const float*)d_in[i]; break;
            case BB * NN * KK:         nbr        = (const int*)d_in[i];   break;
            case BB * NN * KK * CMID:  wn         = (const float*)d_in[i]; break;
            case BB * NN * KK * CADD:  addf       = (const float*)d_in[i]; break;
            case COUT * INF:           W          = (const float*)d_in[i]; break;
            case COUT:                 bias       = (const float*)d_in[i]; break;
            default: break;
        }
    }
    float* out = (float*)d_out;

    cudaFuncSetAttribute(pconv_mma_kernel, cudaFuncAttributeMaxDynamicSharedMemorySize, PCONV_SMEM);
    pconv_mma_kernel<<<(BB * NN) / MTP, 128, PCONV_SMEM>>>(input_feat, nbr, wn, addf);

    wb_kernel<<<(COUT * INFP + 255) / 256, 256>>>(W);

    cudaFuncSetAttribute(gemm_kernel, cudaFuncAttributeMaxDynamicSharedMemorySize, SMEM_GEMM);
    gemm_kernel<<<PTS / 128, 256, SMEM_GEMM>>>(bias, out);
}